// round 13
// baseline (speedup 1.0000x reference)
#include <cuda_runtime.h>
#include <cuda_bf16.h>
#include <cstdint>
#include <math.h>

#define N 8192
#define D 128
#define NCTA 148
#define NTT 2080               /* upper-triangle tiles: 64*65/2 */
#define NTHR 512
#define NBUCK 4096
#define LN2 0.69314718055994531f
#define SQRT_C 4.5398160486f   /* sqrt((1/0.07)*log2(e)) */
#define THRESH 0.1f

// Scratch (no cudaMalloc allowed)
__device__ __nv_bfloat16 g_fraw[N * D];      // normalized * SQRT_C, bf16, original order
__device__ __nv_bfloat16 g_fbs[N * D];       // sorted order, PRE-SWIZZLED block-major (64 x 32KB)
__device__ float g_slab[N];                  // sorted labels
__device__ int   g_sidx[N];                  // sorted -> original index
__device__ float g_den[N];                   // per sorted row
__device__ float g_ps[N];                    // in log2 units
__device__ float g_pc[N];
__device__ float g_loss;
__device__ unsigned g_cnt_gemm, g_cnt_out;

// ---- main kernel SMEM layout (bytes) ----
#define SM_RES   0          /* resident j-strip tile image, 32 KB */
#define SM_STR   32768      /* 2 x 32 KB double-buffered streaming A tile images */
#define SM_LABI  98304      /* 2 x 512B double-buffered row labels */
#define SM_LABJ  99328      /* 512B column labels (per strip) */
#define SM_MBAR  99840      /* 3 mbarriers: B, A0, A1 */
#define SM_TOTAL 99904

__device__ __forceinline__ uint32_t smem_u32(const void* p) {
    uint32_t a;
    asm("{ .reg .u64 t; cvta.to.shared.u64 t, %1; cvt.u32.u64 %0, t; }" : "=r"(a) : "l"(p));
    return a;
}
__device__ __forceinline__ float ex2(float x) {
    float r;
    asm("ex2.approx.ftz.f32 %0, %1;" : "=f"(r) : "f"(x));
    return r;
}
__device__ __forceinline__ unsigned ld_acq(unsigned* p) {
    unsigned v;
    asm volatile("ld.acquire.gpu.u32 %0, [%1];" : "=r"(v) : "l"(p) : "memory");
    return v;
}

#define LDSM_X4(r0, r1, r2, r3, addr) \
    asm volatile("ldmatrix.sync.aligned.m8n8.x4.shared.b16 {%0,%1,%2,%3}, [%4];" \
                 : "=r"(r0), "=r"(r1), "=r"(r2), "=r"(r3) : "r"(addr))

#define MMA16816(d, a, b) \
    asm volatile("mma.sync.aligned.m16n8k16.row.col.f32.bf16.bf16.f32 " \
                 "{%0,%1,%2,%3}, {%4,%5,%6,%7}, {%8,%9}, {%0,%1,%2,%3};" \
                 : "+f"((d)[0]), "+f"((d)[1]), "+f"((d)[2]), "+f"((d)[3]) \
                 : "r"((a)[0]), "r"((a)[1]), "r"((a)[2]), "r"((a)[3]), \
                   "r"((b)[0]), "r"((b)[1]))

#define CP_ASYNC16(dst, src) \
    asm volatile("cp.async.cg.shared.global [%0], [%1], 16;" \
                 :: "r"(dst), "l"(src) : "memory")
#define CP_COMMIT() asm volatile("cp.async.commit_group;" ::: "memory")
#define CP_WAIT0()  asm volatile("cp.async.wait_group 0;" ::: "memory")

#define MBAR_INIT(mbar, cnt) \
    asm volatile("mbarrier.init.shared.b64 [%0], %1;" :: "r"((uint32_t)(mbar)), "r"((uint32_t)(cnt)) : "memory")

__device__ __forceinline__ uint32_t swz(int row, int seg) {
    return (uint32_t)(row * 256 + ((seg ^ (row & 7)) << 4));
}

// single-thread: expect_tx + one 32KB bulk copy of pre-swizzled block blk
__device__ __forceinline__ void tile_load_bulk(uint32_t dst, int blk, uint32_t mbar) {
    size_t src = __cvta_generic_to_global(g_fbs) + (size_t)blk * 32768;
    asm volatile("mbarrier.arrive.expect_tx.shared.b64 _, [%0], %1;"
                 :: "r"(mbar), "r"(32768u) : "memory");
    asm volatile("cp.async.bulk.shared::cluster.global.mbarrier::complete_tx::bytes "
                 "[%0], [%1], %2, [%3];"
                 :: "r"(dst), "l"(src), "r"(32768u), "r"(mbar) : "memory");
}

__device__ __forceinline__ void mbar_wait(uint32_t mbar, uint32_t parity) {
    uint32_t done;
    asm volatile("{\n\t.reg .pred p;\n\t"
        "mbarrier.try_wait.parity.acquire.cta.shared::cta.b64 p, [%1], %2;\n\t"
        "selp.b32 %0, 1, 0, p;\n\t}" : "=r"(done) : "r"(mbar), "r"(parity) : "memory");
    if (!done) {
        asm volatile("{\n\t.reg .pred P1;\n\t"
            "WL_%=:\n\t"
            "mbarrier.try_wait.parity.acquire.cta.shared::cta.b64 P1, [%0], %1, 0x989680;\n\t"
            "@P1 bra.uni WD_%=;\n\t"
            "bra.uni WL_%=;\n\t"
            "WD_%=:\n\t}" :: "r"(mbar), "r"(parity) : "memory");
    }
}

// ---------------------------------------------------------------------------
// Kernel 1 (fused): CTAs 0-255 normalize rows (1 row/warp, 1024 thr) and zero
// state; CTA 256 bucket-sorts (label, idx). Independent work, overlapped.
// ---------------------------------------------------------------------------
__global__ void prep_sort_kernel(const float* __restrict__ features,
                                 const float* __restrict__ labels) {
    extern __shared__ char smem[];
    const int tid = threadIdx.x;

    if (blockIdx.x < 256) {
        // ---- prep ----
        int warp = tid >> 5, lane = tid & 31;
        int row = blockIdx.x * 32 + warp;

        float4 v = ((const float4*)(features + row * D))[lane];
        float ss = v.x * v.x + v.y * v.y + v.z * v.z + v.w * v.w;
        #pragma unroll
        for (int off = 16; off; off >>= 1) ss += __shfl_xor_sync(0xffffffffu, ss, off);
        float sc = SQRT_C / fmaxf(sqrtf(ss), 1e-8f);

        __nv_bfloat162 p0 = __floats2bfloat162_rn(v.x * sc, v.y * sc);
        __nv_bfloat162 p1 = __floats2bfloat162_rn(v.z * sc, v.w * sc);
        uint2 st;
        st.x = *(const uint32_t*)&p0;
        st.y = *(const uint32_t*)&p1;
        ((uint2*)(g_fraw + (size_t)row * D))[lane] = st;

        int gt = blockIdx.x * 1024 + tid;
        if (gt < N) { g_den[gt] = 0.0f; g_ps[gt] = 0.0f; g_pc[gt] = 0.0f; }
        if (gt == 0) { g_loss = 0.0f; g_cnt_gemm = 0u; g_cnt_out = 0u; }
        return;
    }

    // ---- sort (CTA 256) ----
    unsigned long long* keys = (unsigned long long*)smem;       // 64 KB
    unsigned* cnt = (unsigned*)(smem + 65536);                  // 16 KB
    unsigned* bst = (unsigned*)(smem + 65536 + 16384);          // 16 KB
    __shared__ unsigned wtot[33];
    const int wid = tid >> 5, lane = tid & 31;

    for (int b = tid; b < NBUCK; b += 1024) cnt[b] = 0u;
    __syncthreads();
    #pragma unroll
    for (int it = 0; it < 8; it++) {
        float lv = labels[it * 1024 + tid];
        int b = max(0, min(NBUCK - 1, (int)(lv * (float)NBUCK)));
        atomicAdd(&cnt[b], 1u);
    }
    __syncthreads();
    unsigned loc[4]; unsigned s = 0u;
    #pragma unroll
    for (int j = 0; j < 4; j++) { loc[j] = s; s += cnt[tid * 4 + j]; }
    unsigned incl = s;
    #pragma unroll
    for (int off = 1; off < 32; off <<= 1) {
        unsigned v = __shfl_up_sync(0xffffffffu, incl, off);
        if (lane >= off) incl += v;
    }
    if (lane == 31) wtot[wid + 1] = incl;
    if (tid == 0) wtot[0] = 0u;
    __syncthreads();
    if (tid == 0)
        for (int w = 1; w <= 32; w++) wtot[w] += wtot[w - 1];
    __syncthreads();
    unsigned base = wtot[wid] + incl - s;
    #pragma unroll
    for (int j = 0; j < 4; j++) bst[tid * 4 + j] = base + loc[j];
    __syncthreads();
    #pragma unroll
    for (int it = 0; it < 8; it++) {
        int k = it * 1024 + tid;
        float lv = labels[k];
        int b = max(0, min(NBUCK - 1, (int)(lv * (float)NBUCK)));
        unsigned pos = atomicAdd(&bst[b], 1u);
        keys[pos] = ((unsigned long long)__float_as_uint(lv) << 32) | (unsigned)k;
    }
    __syncthreads();
    #pragma unroll 1
    for (int b = tid; b < NBUCK; b += 1024) {
        unsigned st = (b == 0) ? 0u : bst[b - 1];
        unsigned n = cnt[b];
        for (unsigned x = st + 1; x < st + n; x++) {
            unsigned long long v = keys[x];
            unsigned y = x;
            while (y > st && keys[y - 1] > v) { keys[y] = keys[y - 1]; y--; }
            keys[y] = v;
        }
    }
    __syncthreads();
    for (int k = tid; k < N; k += 1024) {
        unsigned long long v = keys[k];
        g_slab[k] = __uint_as_float((unsigned)(v >> 32));
        g_sidx[k] = (int)(v & 0xffffffffu);
    }
}

// ---------------------------------------------------------------------------
// Kernel 2: permute bf16 rows into label-sorted order, PRE-SWIZZLED block-
// major (64 blocks x 32KB = exact smem tile images). 64 CTAs x 256.
// ---------------------------------------------------------------------------
__global__ void perm_kernel() {
    __shared__ int sIdx[128];
    const int tid = threadIdx.x;
    const int c = blockIdx.x;

    if (tid < 128) sIdx[tid] = g_sidx[c * 128 + tid];
    __syncthreads();

    const uint4* src = (const uint4*)g_fraw;           // 16 uint4 per 256B row
    char* dstb = (char*)g_fbs + (size_t)c * 32768;
    #pragma unroll
    for (int it = 0; it < 8; it++) {
        int u = it * 256 + tid;                         // 2048 16B units
        int row = u >> 4, seg = u & 15;
        *(uint4*)(dstb + swz(row, seg)) = src[(size_t)sIdx[row] * 16 + seg];
    }
}

// ---------------------------------------------------------------------------
// Kernel 3: persistent fused HMMA GEMM over the upper triangle in SORTED
// order, column-major strip walk. Tiles loaded with ONE cp.async.bulk each
// (mbarrier completion). Band tiles get the dual ps/pc epilogue; the rest
// denominator-only. Grid barrier + finalize at the tail.
// ---------------------------------------------------------------------------
__global__ void __launch_bounds__(NTHR, 1)
main_kernel(float* __restrict__ out) {
    extern __shared__ char smem[];
    const uint32_t sb = smem_u32(smem);
    const int tid  = threadIdx.x;
    const int wid  = tid >> 5;
    const int lane = tid & 31;
    const int bid  = (int)blockIdx.x;
    const int wm = wid & 3;
    const int wn = wid >> 2;
    const int quad = lane >> 2;
    const int qt   = lane & 3;

    // --- ldmatrix per-lane bases ---
    const int rowA = wm * 32 + (lane & 15);
    const int hiA  = lane >> 4;
    const int r7A  = rowA & 7;
    const uint32_t aRowOff = (uint32_t)(rowA * 256);
    const int g   = lane >> 3;
    const int r8  = lane & 7;
    const int nrowb = wn * 32 + ((g >> 1) << 3) + r8;
    const int segbLo = g & 1;
    const uint32_t bBase = sb + SM_RES + (uint32_t)(nrowb * 256);

    const uint32_t barB  = sb + SM_MBAR;
    const uint32_t barA0 = sb + SM_MBAR + 8;
    const uint32_t barA1 = sb + SM_MBAR + 16;

    const int t0 = ((int)bid * NTT) / NCTA;
    const int t1 = (((int)bid + 1) * NTT) / NCTA;

    int tj = 0, rem = t0;
    while (rem >= tj + 1) { rem -= tj + 1; tj++; }
    int ti = rem;

    size_t slab_g = __cvta_generic_to_global(g_slab);

    if (tid == 0) { MBAR_INIT(barB, 1); MBAR_INIT(barA0, 1); MBAR_INIT(barA1, 1); }
    __syncthreads();

    uint32_t pa0 = 0, pa1 = 0, pb = 0;

    // prologue: resident B(tj) + A(t0) via bulk; labels via cp.async
    if (tid == 0) {
        tile_load_bulk(sb + SM_RES, tj, barB);
        tile_load_bulk(sb + SM_STR + (t0 & 1) * 32768, ti, (t0 & 1) ? barA1 : barA0);
    } else if (tid >= 32 && tid < 64) {
        CP_ASYNC16(sb + SM_LABJ + (tid - 32) * 16,
                   (const void*)(slab_g + (size_t)tj * 512 + (tid - 32) * 16));
    } else if (tid >= 64 && tid < 96) {
        CP_ASYNC16(sb + SM_LABI + (t0 & 1) * 512 + (tid - 64) * 16,
                   (const void*)(slab_g + (size_t)ti * 512 + (tid - 64) * 16));
    }
    CP_COMMIT();
    mbar_wait(barB, 0); pb = 1;
    if (t0 & 1) { mbar_wait(barA1, 0); pa1 = 1; } else { mbar_wait(barA0, 0); pa0 = 1; }
    CP_WAIT0();
    __syncthreads();

    float lj[8];
    #pragma unroll
    for (int p = 0; p < 8; p++)
        lj[p] = ((const float*)(smem + SM_LABJ))[wn * 32 + (p >> 1) * 8 + qt * 2 + (p & 1)];

    float cdn[8], cps[8], cpc[8];
    #pragma unroll
    for (int p = 0; p < 8; p++) { cdn[p] = 0.0f; cps[p] = 0.0f; cpc[p] = 0.0f; }

    for (int t = t0; t < t1; t++) {
        const int s = t & 1;
        const bool have_next = (t + 1) < t1;
        int nti = ti + 1, ntj = tj;
        if (nti > tj) { ntj = tj + 1; nti = 0; }
        const bool strip_change = have_next && (ntj != tj);

        // prefetch A(t+1) (buffer consumed 2 tiles ago, synced) + row labels
        if (have_next) {
            if (tid == 0)
                tile_load_bulk(sb + SM_STR + ((t + 1) & 1) * 32768, nti,
                               ((t + 1) & 1) ? barA1 : barA0);
            else if (tid >= 32 && tid < 64)
                CP_ASYNC16(sb + SM_LABI + ((t + 1) & 1) * 512 + (tid - 32) * 16,
                           (const void*)(slab_g + (size_t)nti * 512 + (tid - 32) * 16));
            CP_COMMIT();
        }

        // wait for A(t) (t0's wait already done in prologue)
        if (t > t0) {
            if (s == 0) { mbar_wait(barA0, pa0); pa0 ^= 1; }
            else        { mbar_wait(barA1, pa1); pa1 ^= 1; }
        }

        // ---- mainloop: 128x128 tile, K=128 ----
        float acc[2][4][4];
        #pragma unroll
        for (int mi = 0; mi < 2; mi++)
            #pragma unroll
            for (int ni = 0; ni < 4; ni++)
                #pragma unroll
                for (int r = 0; r < 4; r++) acc[mi][ni][r] = 0.0f;

        const uint32_t aBase = sb + SM_STR + s * 32768 + aRowOff;
        #pragma unroll
        for (int k = 0; k < 8; k++) {
            uint32_t a[2][4];
            #pragma unroll
            for (int mi = 0; mi < 2; mi++) {
                uint32_t addr = aBase + mi * 4096 + ((((k * 2 + hiA) ^ r7A)) << 4);
                LDSM_X4(a[mi][0], a[mi][1], a[mi][2], a[mi][3], addr);
            }
            uint32_t b[4][2];
            #pragma unroll
            for (int p = 0; p < 2; p++) {
                uint32_t addr = bBase + p * 4096 + ((((k * 2 + segbLo) ^ r8)) << 4);
                LDSM_X4(b[2 * p][0], b[2 * p][1], b[2 * p + 1][0], b[2 * p + 1][1], addr);
            }
            #pragma unroll
            for (int mi = 0; mi < 2; mi++)
                #pragma unroll
                for (int ni = 0; ni < 4; ni++)
                    MMA16816(acc[mi][ni], a[mi], b[ni]);
        }

        const float* slabI = (const float*)(smem + SM_LABI + s * 512);
        const bool band = (ti == tj) ||
            (((const float*)(smem + SM_LABJ))[0] - slabI[127] < THRESH);

        float li[4];
        #pragma unroll
        for (int s2 = 0; s2 < 4; s2++)
            li[s2] = slabI[wm * 32 + (s2 >> 1) * 16 + quad + (s2 & 1) * 8];

        // ---- fused epilogue (acc is already the ex2 argument, log2 units) ----
        float dn[4] = {0, 0, 0, 0}, ps[4] = {0, 0, 0, 0}, pc[4] = {0, 0, 0, 0};
        if (ti == tj) {
            #pragma unroll
            for (int mi = 0; mi < 2; mi++) {
                #pragma unroll
                for (int rh = 0; rh < 2; rh++) {
                    const int slot = mi * 2 + rh;
                    const int selfnl = wm * 32 + mi * 16 + quad + rh * 8;
                    const float lm = li[slot];
                    #pragma unroll
                    for (int p = 0; p < 8; p++) {
                        const int ni = p >> 1, c = p & 1;
                        float u = acc[mi][ni][rh * 2 + c];
                        const int nl = wn * 32 + ni * 8 + qt * 2 + c;
                        bool self = (nl == selfnl);
                        float e = ex2(u);
                        dn[slot] += self ? 0.0f : e;
                        bool pos = (fabsf(lm - lj[p]) < THRESH) && !self;
                        ps[slot] += pos ? u : 0.0f;
                        pc[slot] += pos ? 1.0f : 0.0f;
                    }
                }
            }
        } else if (band) {
            #pragma unroll
            for (int p = 0; p < 8; p++) {
                const int ni = p >> 1, c = p & 1;
                const float ljp = lj[p];
                float a0 = 0.0f, a1 = 0.0f, a2 = 0.0f;
                #pragma unroll
                for (int mi = 0; mi < 2; mi++) {
                    #pragma unroll
                    for (int rh = 0; rh < 2; rh++) {
                        const int slot = mi * 2 + rh;
                        float u = acc[mi][ni][rh * 2 + c];
                        float e = ex2(u);
                        dn[slot] += e;
                        a0 += e;
                        bool pos = fabsf(li[slot] - ljp) < THRESH;
                        float up = pos ? u : 0.0f;
                        float op = pos ? 1.0f : 0.0f;
                        ps[slot] += up;  a1 += up;
                        pc[slot] += op;  a2 += op;
                    }
                }
                cdn[p] += a0; cps[p] += a1; cpc[p] += a2;
            }
        } else {
            #pragma unroll
            for (int p = 0; p < 8; p++) {
                const int ni = p >> 1, c = p & 1;
                float a0 = 0.0f;
                #pragma unroll
                for (int mi = 0; mi < 2; mi++) {
                    #pragma unroll
                    for (int rh = 0; rh < 2; rh++) {
                        float e = ex2(acc[mi][ni][rh * 2 + c]);
                        dn[mi * 2 + rh] += e;
                        a0 += e;
                    }
                }
                cdn[p] += a0;
            }
        }

        // ---- row flush (2-round qt shuffle) ----
        #pragma unroll
        for (int s2 = 0; s2 < 4; s2++) {
            float a = dn[s2];
            a += __shfl_xor_sync(0xffffffffu, a, 1);
            a += __shfl_xor_sync(0xffffffffu, a, 2);
            int gim = ti * 128 + wm * 32 + (s2 >> 1) * 16 + quad + (s2 & 1) * 8;
            if (band) {
                float b2 = ps[s2], c2 = pc[s2];
                b2 += __shfl_xor_sync(0xffffffffu, b2, 1);
                b2 += __shfl_xor_sync(0xffffffffu, b2, 2);
                c2 += __shfl_xor_sync(0xffffffffu, c2, 1);
                c2 += __shfl_xor_sync(0xffffffffu, c2, 2);
                if (qt == 0) {
                    atomicAdd(&g_den[gim], a);
                    atomicAdd(&g_ps[gim],  b2);
                    atomicAdd(&g_pc[gim],  c2);
                }
            } else if (qt == 0) {
                atomicAdd(&g_den[gim], a);
            }
        }

        // ---- column flush at strip end / range end ----
        if (strip_change || !have_next) {
            #pragma unroll
            for (int p = 0; p < 8; p++) {
                float a = cdn[p], b2 = cps[p], c2 = cpc[p];
                #pragma unroll
                for (int off = 4; off <= 16; off <<= 1) {
                    a  += __shfl_xor_sync(0xffffffffu, a, off);
                    b2 += __shfl_xor_sync(0xffffffffu, b2, off);
                    c2 += __shfl_xor_sync(0xffffffffu, c2, off);
                }
                if (quad == 0) {
                    int gj = tj * 128 + wn * 32 + (p >> 1) * 8 + qt * 2 + (p & 1);
                    atomicAdd(&g_den[gj], a);
                    atomicAdd(&g_ps[gj],  b2);
                    atomicAdd(&g_pc[gj],  c2);
                }
                cdn[p] = 0.0f; cps[p] = 0.0f; cpc[p] = 0.0f;
            }
        }

        CP_WAIT0();            // labels(t+1) landed
        __syncthreads();       // all reads of A-buf / RES / labels done

        if (strip_change) {
            if (tid == 0) tile_load_bulk(sb + SM_RES, ntj, barB);
            else if (tid >= 32 && tid < 64)
                CP_ASYNC16(sb + SM_LABJ + (tid - 32) * 16,
                           (const void*)(slab_g + (size_t)ntj * 512 + (tid - 32) * 16));
            CP_COMMIT();
            mbar_wait(barB, pb); pb ^= 1;
            CP_WAIT0();
            __syncthreads();
            #pragma unroll
            for (int p = 0; p < 8; p++)
                lj[p] = ((const float*)(smem + SM_LABJ))[wn * 32 + (p >> 1) * 8 + qt * 2 + (p & 1)];
        }
        ti = nti; tj = ntj;
    }

    // ===================== grid barrier =====================
    __threadfence();
    __syncthreads();
    if (tid == 0) {
        atomicAdd(&g_cnt_gemm, 1u);
        while (ld_acq(&g_cnt_gemm) < (unsigned)NCTA) __nanosleep(128);
    }
    __syncthreads();

    // ===================== finalize =====================
    {
        int r = bid * NTHR + tid;           // one row per thread; bid<16 active
        float term = 0.0f;
        if (r < N)
            term = g_ps[r] / g_pc[r] - log2f(g_den[r]);
        #pragma unroll
        for (int off = 16; off; off >>= 1)
            term += __shfl_xor_sync(0xffffffffu, term, off);
        if (lane == 0 && (bid * NTHR + wid * 32) < N)
            atomicAdd(&g_loss, term);

        __threadfence();
        __syncthreads();
        if (tid == 0) {
            unsigned tk = atomicAdd(&g_cnt_out, 1u);
            if (tk == (unsigned)(NCTA - 1))
                out[0] = -(LN2 * atomicAdd(&g_loss, 0.0f)) / (float)N;
        }
    }
}

// ---------------------------------------------------------------------------
extern "C" void kernel_launch(void* const* d_in, const int* in_sizes, int n_in,
                              void* d_out, int out_size) {
    const float* features = (const float*)d_in[0];
    const float* labels   = (const float*)d_in[1];
    float* out = (float*)d_out;

    cudaFuncSetAttribute(main_kernel, cudaFuncAttributeMaxDynamicSharedMemorySize, SM_TOTAL);
    cudaFuncSetAttribute(prep_sort_kernel, cudaFuncAttributeMaxDynamicSharedMemorySize, 98304);

    prep_sort_kernel<<<257, 1024, 98304>>>(features, labels);
    perm_kernel<<<64, 256>>>();
    main_kernel<<<NCTA, NTHR, SM_TOTAL>>>(out);
}

// round 15
// speedup vs baseline: 1.0685x; 1.0685x over previous
#include <cuda_runtime.h>
#include <cuda_bf16.h>
#include <cstdint>
#include <math.h>

#define N 8192
#define D 128
#define NCTA 148
#define NTHR 512
#define NBUCK 4096
#define WTOT 7850              /* sum of tile weights: 3*2080 + 2*805 */
#define LN2 0.69314718055994531f
#define SQRT_C 4.5398160486f   /* sqrt((1/0.07)*log2(e)) */
#define THRESH 0.1f

// Scratch (no cudaMalloc allowed)
__device__ __nv_bfloat16 g_fraw[N * D];      // normalized * SQRT_C, bf16, original order
__device__ __nv_bfloat16 g_fbs[N * D];       // sorted order, PRE-SWIZZLED block-major (64 x 32KB)
__device__ float g_slab[N];                  // sorted labels
__device__ int   g_sidx[N];                  // sorted -> original index
__device__ float g_den[N];                   // per sorted row
__device__ float g_ps[N];                    // in log2 units
__device__ float g_pc[N];
__device__ float g_loss;
__device__ unsigned g_cnt_gemm, g_cnt_out;

// ---- main kernel SMEM layout (bytes) ----
#define SM_RES   0          /* resident j-strip tile image, 32 KB */
#define SM_STR   32768      /* 2 x 32 KB double-buffered streaming A tile images */
#define SM_LABI  98304      /* 2 x 512B double-buffered row labels */
#define SM_LABJ  99328      /* 512B column labels (per strip) */
#define SM_MBAR  99840      /* 3 mbarriers: B, A0, A1 */
#define SM_TOTAL 99904

__device__ __forceinline__ uint32_t smem_u32(const void* p) {
    uint32_t a;
    asm("{ .reg .u64 t; cvta.to.shared.u64 t, %1; cvt.u32.u64 %0, t; }" : "=r"(a) : "l"(p));
    return a;
}
__device__ __forceinline__ float ex2(float x) {
    float r;
    asm("ex2.approx.ftz.f32 %0, %1;" : "=f"(r) : "f"(x));
    return r;
}
__device__ __forceinline__ unsigned ld_acq(unsigned* p) {
    unsigned v;
    asm volatile("ld.acquire.gpu.u32 %0, [%1];" : "=r"(v) : "l"(p) : "memory");
    return v;
}

#define LDSM_X4(r0, r1, r2, r3, addr) \
    asm volatile("ldmatrix.sync.aligned.m8n8.x4.shared.b16 {%0,%1,%2,%3}, [%4];" \
                 : "=r"(r0), "=r"(r1), "=r"(r2), "=r"(r3) : "r"(addr))

#define MMA16816(d, a, b) \
    asm volatile("mma.sync.aligned.m16n8k16.row.col.f32.bf16.bf16.f32 " \
                 "{%0,%1,%2,%3}, {%4,%5,%6,%7}, {%8,%9}, {%0,%1,%2,%3};" \
                 : "+f"((d)[0]), "+f"((d)[1]), "+f"((d)[2]), "+f"((d)[3]) \
                 : "r"((a)[0]), "r"((a)[1]), "r"((a)[2]), "r"((a)[3]), \
                   "r"((b)[0]), "r"((b)[1]))

#define CP_ASYNC16(dst, src) \
    asm volatile("cp.async.cg.shared.global [%0], [%1], 16;" \
                 :: "r"(dst), "l"(src) : "memory")
#define CP_COMMIT() asm volatile("cp.async.commit_group;" ::: "memory")
#define CP_WAIT0()  asm volatile("cp.async.wait_group 0;" ::: "memory")

#define MBAR_INIT(mbar, cnt) \
    asm volatile("mbarrier.init.shared.b64 [%0], %1;" :: "r"((uint32_t)(mbar)), "r"((uint32_t)(cnt)) : "memory")

__device__ __forceinline__ uint32_t swz(int row, int seg) {
    return (uint32_t)(row * 256 + ((seg ^ (row & 7)) << 4));
}

// single-thread: expect_tx + one 32KB bulk copy of pre-swizzled block blk
__device__ __forceinline__ void tile_load_bulk(uint32_t dst, int blk, uint32_t mbar) {
    size_t src = __cvta_generic_to_global(g_fbs) + (size_t)blk * 32768;
    asm volatile("mbarrier.arrive.expect_tx.shared.b64 _, [%0], %1;"
                 :: "r"(mbar), "r"(32768u) : "memory");
    asm volatile("cp.async.bulk.shared::cluster.global.mbarrier::complete_tx::bytes "
                 "[%0], [%1], %2, [%3];"
                 :: "r"(dst), "l"(src), "r"(32768u), "r"(mbar) : "memory");
}

__device__ __forceinline__ void mbar_wait(uint32_t mbar, uint32_t parity) {
    uint32_t done;
    asm volatile("{\n\t.reg .pred p;\n\t"
        "mbarrier.try_wait.parity.acquire.cta.shared::cta.b64 p, [%1], %2;\n\t"
        "selp.b32 %0, 1, 0, p;\n\t}" : "=r"(done) : "r"(mbar), "r"(parity) : "memory");
    if (!done) {
        asm volatile("{\n\t.reg .pred P1;\n\t"
            "WL_%=:\n\t"
            "mbarrier.try_wait.parity.acquire.cta.shared::cta.b64 P1, [%0], %1, 0x989680;\n\t"
            "@P1 bra.uni WD_%=;\n\t"
            "bra.uni WL_%=;\n\t"
            "WD_%=:\n\t}" :: "r"(mbar), "r"(parity) : "memory");
    }
}

__device__ __forceinline__ int tile_w(int tj, int ti) { return (tj - ti) <= 13 ? 5 : 3; }
__device__ __forceinline__ int strip_w(int tj) {
    int m = (tj + 1) < 14 ? (tj + 1) : 14;
    return 3 * (tj + 1) + 2 * m;
}

// ---------------------------------------------------------------------------
// Kernel 1 (fused): CTAs 0-255 normalize rows and zero state; CTA 256 sorts.
// ---------------------------------------------------------------------------
__global__ void prep_sort_kernel(const float* __restrict__ features,
                                 const float* __restrict__ labels) {
    extern __shared__ char smem[];
    const int tid = threadIdx.x;

    if (blockIdx.x < 256) {
        int warp = tid >> 5, lane = tid & 31;
        int row = blockIdx.x * 32 + warp;

        float4 v = ((const float4*)(features + row * D))[lane];
        float ss = v.x * v.x + v.y * v.y + v.z * v.z + v.w * v.w;
        #pragma unroll
        for (int off = 16; off; off >>= 1) ss += __shfl_xor_sync(0xffffffffu, ss, off);
        float sc = SQRT_C / fmaxf(sqrtf(ss), 1e-8f);

        __nv_bfloat162 p0 = __floats2bfloat162_rn(v.x * sc, v.y * sc);
        __nv_bfloat162 p1 = __floats2bfloat162_rn(v.z * sc, v.w * sc);
        uint2 st;
        st.x = *(const uint32_t*)&p0;
        st.y = *(const uint32_t*)&p1;
        ((uint2*)(g_fraw + (size_t)row * D))[lane] = st;

        int gt = blockIdx.x * 1024 + tid;
        if (gt < N) { g_den[gt] = 0.0f; g_ps[gt] = 0.0f; g_pc[gt] = 0.0f; }
        if (gt == 0) { g_loss = 0.0f; g_cnt_gemm = 0u; g_cnt_out = 0u; }
        return;
    }

    // ---- sort (CTA 256) ----
    unsigned long long* keys = (unsigned long long*)smem;       // 64 KB
    unsigned* cnt = (unsigned*)(smem + 65536);                  // 16 KB
    unsigned* bst = (unsigned*)(smem + 65536 + 16384);          // 16 KB
    __shared__ unsigned wtot[33];
    const int wid = tid >> 5, lane = tid & 31;

    for (int b = tid; b < NBUCK; b += 1024) cnt[b] = 0u;
    __syncthreads();
    #pragma unroll
    for (int it = 0; it < 8; it++) {
        float lv = labels[it * 1024 + tid];
        int b = max(0, min(NBUCK - 1, (int)(lv * (float)NBUCK)));
        atomicAdd(&cnt[b], 1u);
    }
    __syncthreads();
    unsigned loc[4]; unsigned s = 0u;
    #pragma unroll
    for (int j = 0; j < 4; j++) { loc[j] = s; s += cnt[tid * 4 + j]; }
    unsigned incl = s;
    #pragma unroll
    for (int off = 1; off < 32; off <<= 1) {
        unsigned v = __shfl_up_sync(0xffffffffu, incl, off);
        if (lane >= off) incl += v;
    }
    if (lane == 31) wtot[wid + 1] = incl;
    if (tid == 0) wtot[0] = 0u;
    __syncthreads();
    if (tid == 0)
        for (int w = 1; w <= 32; w++) wtot[w] += wtot[w - 1];
    __syncthreads();
    unsigned base = wtot[wid] + incl - s;
    #pragma unroll
    for (int j = 0; j < 4; j++) bst[tid * 4 + j] = base + loc[j];
    __syncthreads();
    #pragma unroll
    for (int it = 0; it < 8; it++) {
        int k = it * 1024 + tid;
        float lv = labels[k];
        int b = max(0, min(NBUCK - 1, (int)(lv * (float)NBUCK)));
        unsigned pos = atomicAdd(&bst[b], 1u);
        keys[pos] = ((unsigned long long)__float_as_uint(lv) << 32) | (unsigned)k;
    }
    __syncthreads();
    #pragma unroll 1
    for (int b = tid; b < NBUCK; b += 1024) {
        unsigned st = (b == 0) ? 0u : bst[b - 1];
        unsigned n = cnt[b];
        for (unsigned x = st + 1; x < st + n; x++) {
            unsigned long long v = keys[x];
            unsigned y = x;
            while (y > st && keys[y - 1] > v) { keys[y] = keys[y - 1]; y--; }
            keys[y] = v;
        }
    }
    __syncthreads();
    for (int k = tid; k < N; k += 1024) {
        unsigned long long v = keys[k];
        g_slab[k] = __uint_as_float((unsigned)(v >> 32));
        g_sidx[k] = (int)(v & 0xffffffffu);
    }
}

// ---------------------------------------------------------------------------
// Kernel 2: permute bf16 rows into sorted order, pre-swizzled block-major.
// ---------------------------------------------------------------------------
__global__ void perm_kernel() {
    __shared__ int sIdx[128];
    const int tid = threadIdx.x;
    const int c = blockIdx.x;

    if (tid < 128) sIdx[tid] = g_sidx[c * 128 + tid];
    __syncthreads();

    const uint4* src = (const uint4*)g_fraw;
    char* dstb = (char*)g_fbs + (size_t)c * 32768;
    #pragma unroll
    for (int it = 0; it < 8; it++) {
        int u = it * 256 + tid;
        int row = u >> 4, seg = u & 15;
        *(uint4*)(dstb + swz(row, seg)) = src[(size_t)sIdx[row] * 16 + seg];
    }
}

// ---------------------------------------------------------------------------
// Kernel 3: persistent fused HMMA GEMM, upper triangle in sorted order,
// column-major strip walk, COST-WEIGHTED static partition with consistent
// cumBefore ownership: tile t -> bid iff bid*WTOT <= cumBefore(t)*NCTA.
// ---------------------------------------------------------------------------
__global__ void __launch_bounds__(NTHR, 1)
main_kernel(float* __restrict__ out) {
    extern __shared__ char smem[];
    const uint32_t sb = smem_u32(smem);
    const int tid  = threadIdx.x;
    const int wid  = tid >> 5;
    const int lane = tid & 31;
    const int bid  = (int)blockIdx.x;
    const int wm = wid & 3;
    const int wn = wid >> 2;
    const int quad = lane >> 2;
    const int qt   = lane & 3;

    // --- ldmatrix per-lane bases ---
    const int rowA = wm * 32 + (lane & 15);
    const int hiA  = lane >> 4;
    const int r7A  = rowA & 7;
    const uint32_t aRowOff = (uint32_t)(rowA * 256);
    const int g   = lane >> 3;
    const int r8  = lane & 7;
    const int nrowb = wn * 32 + ((g >> 1) << 3) + r8;
    const int segbLo = g & 1;
    const uint32_t bBase = sb + SM_RES + (uint32_t)(nrowb * 256);

    const uint32_t barB  = sb + SM_MBAR;
    const uint32_t barA0 = sb + SM_MBAR + 8;
    const uint32_t barA1 = sb + SM_MBAR + 16;

    // ---- weighted partition (cumBefore ownership, exact & disjoint) ----
    const long long bw0 = (long long)bid * WTOT;
    const long long bw1 = (long long)(bid + 1) * WTOT;
    int cw = 0, tj = 0;
    while ((long long)(cw + strip_w(tj)) * NCTA <= bw0) { cw += strip_w(tj); tj++; }
    int ti = 0;
    while ((long long)cw * NCTA < bw0) { cw += tile_w(tj, ti); ti++; }
    if (ti > tj) { tj++; ti = 0; }   // boundary landed exactly on a strip edge

    size_t slab_g = __cvta_generic_to_global(g_slab);

    if (tid == 0) { MBAR_INIT(barB, 1); MBAR_INIT(barA0, 1); MBAR_INIT(barA1, 1); }
    __syncthreads();

    uint32_t pa0 = 0, pa1 = 0, pb = 0;
    int bs = 0;

    // prologue: resident B(tj) + A(ti) into buffer 0
    if (tid == 0) {
        tile_load_bulk(sb + SM_RES, tj, barB);
        tile_load_bulk(sb + SM_STR, ti, barA0);
    } else if (tid >= 32 && tid < 64) {
        CP_ASYNC16(sb + SM_LABJ + (tid - 32) * 16,
                   (const void*)(slab_g + (size_t)tj * 512 + (tid - 32) * 16));
    } else if (tid >= 64 && tid < 96) {
        CP_ASYNC16(sb + SM_LABI + (tid - 64) * 16,
                   (const void*)(slab_g + (size_t)ti * 512 + (tid - 64) * 16));
    }
    CP_COMMIT();
    mbar_wait(barB, 0); pb = 1;
    mbar_wait(barA0, 0); pa0 = 1;
    CP_WAIT0();
    __syncthreads();

    float lj[8];
    #pragma unroll
    for (int p = 0; p < 8; p++)
        lj[p] = ((const float*)(smem + SM_LABJ))[wn * 32 + (p >> 1) * 8 + qt * 2 + (p & 1)];

    float cdn[8], cps[8], cpc[8];
    #pragma unroll
    for (int p = 0; p < 8; p++) { cdn[p] = 0.0f; cps[p] = 0.0f; cpc[p] = 0.0f; }

    bool first = true;
    while (true) {
        const int s = bs;
        const long long ncw = cw + tile_w(tj, ti);    // cumBefore of next tile
        const bool have_next = ncw * NCTA < bw1;
        int nti = ti + 1, ntj = tj;
        if (nti > tj) { ntj = tj + 1; nti = 0; }
        const bool strip_change = have_next && (ntj != tj);

        // prefetch A(next) into the other buffer + its row labels
        if (have_next) {
            if (tid == 0)
                tile_load_bulk(sb + SM_STR + (bs ^ 1) * 32768, nti, (bs ^ 1) ? barA1 : barA0);
            else if (tid >= 32 && tid < 64)
                CP_ASYNC16(sb + SM_LABI + (bs ^ 1) * 512 + (tid - 32) * 16,
                           (const void*)(slab_g + (size_t)nti * 512 + (tid - 32) * 16));
            CP_COMMIT();
        }

        // wait for current A buffer (first tile already waited in prologue)
        if (!first) {
            if (s == 0) { mbar_wait(barA0, pa0); pa0 ^= 1; }
            else        { mbar_wait(barA1, pa1); pa1 ^= 1; }
        }

        // ---- mainloop: 128x128 tile, K=128 ----
        float acc[2][4][4];
        #pragma unroll
        for (int mi = 0; mi < 2; mi++)
            #pragma unroll
            for (int ni = 0; ni < 4; ni++)
                #pragma unroll
                for (int r = 0; r < 4; r++) acc[mi][ni][r] = 0.0f;

        const uint32_t aBase = sb + SM_STR + s * 32768 + aRowOff;
        #pragma unroll
        for (int k = 0; k < 8; k++) {
            uint32_t a[2][4];
            #pragma unroll
            for (int mi = 0; mi < 2; mi++) {
                uint32_t addr = aBase + mi * 4096 + ((((k * 2 + hiA) ^ r7A)) << 4);
                LDSM_X4(a[mi][0], a[mi][1], a[mi][2], a[mi][3], addr);
            }
            uint32_t b[4][2];
            #pragma unroll
            for (int p = 0; p < 2; p++) {
                uint32_t addr = bBase + p * 4096 + ((((k * 2 + segbLo) ^ r8)) << 4);
                LDSM_X4(b[2 * p][0], b[2 * p][1], b[2 * p + 1][0], b[2 * p + 1][1], addr);
            }
            #pragma unroll
            for (int mi = 0; mi < 2; mi++)
                #pragma unroll
                for (int ni = 0; ni < 4; ni++)
                    MMA16816(acc[mi][ni], a[mi], b[ni]);
        }

        const float* slabI = (const float*)(smem + SM_LABI + s * 512);
        const bool band = (ti == tj) ||
            (((const float*)(smem + SM_LABJ))[0] - slabI[127] < THRESH);

        float li[4];
        #pragma unroll
        for (int s2 = 0; s2 < 4; s2++)
            li[s2] = slabI[wm * 32 + (s2 >> 1) * 16 + quad + (s2 & 1) * 8];

        // ---- fused epilogue (acc is already the ex2 argument, log2 units) ----
        float dn[4] = {0, 0, 0, 0}, ps[4] = {0, 0, 0, 0}, pc[4] = {0, 0, 0, 0};
        if (ti == tj) {
            #pragma unroll
            for (int mi = 0; mi < 2; mi++) {
                #pragma unroll
                for (int rh = 0; rh < 2; rh++) {
                    const int slot = mi * 2 + rh;
                    const int selfnl = wm * 32 + mi * 16 + quad + rh * 8;
                    const float lm = li[slot];
                    #pragma unroll
                    for (int p = 0; p < 8; p++) {
                        const int ni = p >> 1, c = p & 1;
                        float u = acc[mi][ni][rh * 2 + c];
                        const int nl = wn * 32 + ni * 8 + qt * 2 + c;
                        bool self = (nl == selfnl);
                        float e = ex2(u);
                        dn[slot] += self ? 0.0f : e;
                        bool pos = (fabsf(lm - lj[p]) < THRESH) && !self;
                        ps[slot] += pos ? u : 0.0f;
                        pc[slot] += pos ? 1.0f : 0.0f;
                    }
                }
            }
        } else if (band) {
            #pragma unroll
            for (int p = 0; p < 8; p++) {
                const int ni = p >> 1, c = p & 1;
                const float ljp = lj[p];
                float a0 = 0.0f, a1 = 0.0f, a2 = 0.0f;
                #pragma unroll
                for (int mi = 0; mi < 2; mi++) {
                    #pragma unroll
                    for (int rh = 0; rh < 2; rh++) {
                        const int slot = mi * 2 + rh;
                        float u = acc[mi][ni][rh * 2 + c];
                        float e = ex2(u);
                        dn[slot] += e;
                        a0 += e;
                        bool pos = fabsf(li[slot] - ljp) < THRESH;
                        float up = pos ? u : 0.0f;
                        float op = pos ? 1.0f : 0.0f;
                        ps[slot] += up;  a1 += up;
                        pc[slot] += op;  a2 += op;
                    }
                }
                cdn[p] += a0; cps[p] += a1; cpc[p] += a2;
            }
        } else {
            #pragma unroll
            for (int p = 0; p < 8; p++) {
                const int ni = p >> 1, c = p & 1;
                float a0 = 0.0f;
                #pragma unroll
                for (int mi = 0; mi < 2; mi++) {
                    #pragma unroll
                    for (int rh = 0; rh < 2; rh++) {
                        float e = ex2(acc[mi][ni][rh * 2 + c]);
                        dn[mi * 2 + rh] += e;
                        a0 += e;
                    }
                }
                cdn[p] += a0;
            }
        }

        // ---- row flush (2-round qt shuffle) ----
        #pragma unroll
        for (int s2 = 0; s2 < 4; s2++) {
            float a = dn[s2];
            a += __shfl_xor_sync(0xffffffffu, a, 1);
            a += __shfl_xor_sync(0xffffffffu, a, 2);
            int gim = ti * 128 + wm * 32 + (s2 >> 1) * 16 + quad + (s2 & 1) * 8;
            if (band) {
                float b2 = ps[s2], c2 = pc[s2];
                b2 += __shfl_xor_sync(0xffffffffu, b2, 1);
                b2 += __shfl_xor_sync(0xffffffffu, b2, 2);
                c2 += __shfl_xor_sync(0xffffffffu, c2, 1);
                c2 += __shfl_xor_sync(0xffffffffu, c2, 2);
                if (qt == 0) {
                    atomicAdd(&g_den[gim], a);
                    atomicAdd(&g_ps[gim],  b2);
                    atomicAdd(&g_pc[gim],  c2);
                }
            } else if (qt == 0) {
                atomicAdd(&g_den[gim], a);
            }
        }

        // ---- column flush at strip end / range end ----
        if (strip_change || !have_next) {
            #pragma unroll
            for (int p = 0; p < 8; p++) {
                float a = cdn[p], b2 = cps[p], c2 = cpc[p];
                #pragma unroll
                for (int off = 4; off <= 16; off <<= 1) {
                    a  += __shfl_xor_sync(0xffffffffu, a, off);
                    b2 += __shfl_xor_sync(0xffffffffu, b2, off);
                    c2 += __shfl_xor_sync(0xffffffffu, c2, off);
                }
                if (quad == 0) {
                    int gj = tj * 128 + wn * 32 + (p >> 1) * 8 + qt * 2 + (p & 1);
                    atomicAdd(&g_den[gj], a);
                    atomicAdd(&g_ps[gj],  b2);
                    atomicAdd(&g_pc[gj],  c2);
                }
                cdn[p] = 0.0f; cps[p] = 0.0f; cpc[p] = 0.0f;
            }
        }

        CP_WAIT0();            // labels(next) landed
        __syncthreads();       // all reads of A-buf / RES / labels done

        if (!have_next) break;

        if (strip_change) {
            if (tid == 0) tile_load_bulk(sb + SM_RES, ntj, barB);
            else if (tid >= 32 && tid < 64)
                CP_ASYNC16(sb + SM_LABJ + (tid - 32) * 16,
                           (const void*)(slab_g + (size_t)ntj * 512 + (tid - 32) * 16));
            CP_COMMIT();
            mbar_wait(barB, pb); pb ^= 1;
            CP_WAIT0();
            __syncthreads();
            #pragma unroll
            for (int p = 0; p < 8; p++)
                lj[p] = ((const float*)(smem + SM_LABJ))[wn * 32 + (p >> 1) * 8 + qt * 2 + (p & 1)];
        }
        ti = nti; tj = ntj; cw = (int)ncw; bs ^= 1; first = false;
    }

    // ===================== grid barrier =====================
    __threadfence();
    __syncthreads();
    if (tid == 0) {
        atomicAdd(&g_cnt_gemm, 1u);
        while (ld_acq(&g_cnt_gemm) < (unsigned)NCTA) __nanosleep(128);
    }
    __syncthreads();

    // ===================== finalize =====================
    {
        int r = bid * NTHR + tid;           // one row per thread; bid<16 active
        float term = 0.0f;
        if (r < N)
            term = g_ps[r] / g_pc[r] - log2f(g_den[r]);
        #pragma unroll
        for (int off = 16; off; off >>= 1)
            term += __shfl_xor_sync(0xffffffffu, term, off);
        if (lane == 0 && (bid * NTHR + wid * 32) < N)
            atomicAdd(&g_loss, term);

        __threadfence();
        __syncthreads();
        if (tid == 0) {
            unsigned tk = atomicAdd(&g_cnt_out, 1u);
            if (tk == (unsigned)(NCTA - 1))
                out[0] = -(LN2 * atomicAdd(&g_loss, 0.0f)) / (float)N;
        }
    }
}

// ---------------------------------------------------------------------------
extern "C" void kernel_launch(void* const* d_in, const int* in_sizes, int n_in,
                              void* d_out, int out_size) {
    const float* features = (const float*)d_in[0];
    const float* labels   = (const float*)d_in[1];
    float* out = (float*)d_out;

    cudaFuncSetAttribute(main_kernel, cudaFuncAttributeMaxDynamicSharedMemorySize, SM_TOTAL);
    cudaFuncSetAttribute(prep_sort_kernel, cudaFuncAttributeMaxDynamicSharedMemorySize, 98304);

    prep_sort_kernel<<<257, 1024, 98304>>>(features, labels);
    perm_kernel<<<64, 256>>>();
    main_kernel<<<NCTA, NTHR, SM_TOTAL>>>(out);
}